// round 14
// baseline (speedup 1.0000x reference)
#include <cuda_runtime.h>
#include <cuda_fp16.h>
#include <cstdint>

#define NNODES 50000
#define EDGES 800000
#define FIN 256
#define HID 256
#define NCAT 1024
#define NCLS 40
#define CLSP 48
#define BN_EPS 1e-5f
#define NTOT (4 * NNODES)
#define ETOT (4 * EDGES)
#define CLS_BLOCKS ((NNODES + 127) / 128)

// ---------------- scratch (static device globals) ---------------------------
__device__ __half g_T1h[(size_t)NNODES * NCAT];
__device__ __half g_AGGh[(size_t)NNODES * NCAT];
__device__ int   g_cnt[NTOT];
__device__ float g_dinv[NTOT];
__device__ float g_invdeg[NTOT];
__device__ int   g_start[NTOT + 1];
__device__ int   g_cursor[NTOT];
__device__ int   g_bsum[1024];
__device__ uint2 g_edge[ETOT];          // {src, weight bits} packed
__device__ float g_mask[4];
__device__ float g_bn1s[HID], g_bn1t[HID], g_bn2s[HID], g_bn2t[HID];
__device__ __half g_xh[(size_t)NNODES * FIN];
__device__ __half g_Wch[FIN * NCAT];
__device__ __half g_W2h[HID * HID];
__device__ __half g_Wc48[NCAT * CLSP];
__device__ float g_part[(size_t)CLS_BLOCKS * 256 * 24];

// ---------------- tiny prep kernels -----------------------------------------
__global__ void params_kernel(const float* __restrict__ att,
                              const float* g1, const float* b1, const float* m1, const float* v1,
                              const float* g2, const float* b2, const float* m2, const float* v2) {
    int i = threadIdx.x;
    if (i < HID) {
        float s1 = g1[i] * rsqrtf(v1[i] + BN_EPS);
        g_bn1s[i] = s1; g_bn1t[i] = b1[i] - m1[i] * s1;
        float s2 = g2[i] * rsqrtf(v2[i] + BN_EPS);
        g_bn2s[i] = s2; g_bn2t[i] = b2[i] - m2[i] * s2;
    }
    if (i == 0) {
        float m = att[0];
        for (int k = 1; k < 4; k++) m = fmaxf(m, att[k]);
        float s = 0.f, e[4];
        for (int k = 0; k < 4; k++) { e[k] = expf(att[k] - m); s += e[k]; }
        for (int k = 0; k < 4; k++) g_mask[k] = e[k] / s;
    }
}

__global__ void zero_cnt_kernel() {
    int i = blockIdx.x * blockDim.x + threadIdx.x;
    if (i < NTOT) g_cnt[i] = 0;
}

__global__ void count_deg_kernel(const int* __restrict__ adj) {
    int i = blockIdx.x * blockDim.x + threadIdx.x;
    if (i >= ETOT) return;
    int j = i / EDGES;
    int e = i - j * EDGES;
    int dst = adj[(size_t)j * 2 * EDGES + EDGES + e];
    atomicAdd(&g_cnt[j * NNODES + dst], 1);
}

__global__ void scanA_kernel() {
    __shared__ int sh[256];
    int i = blockIdx.x * 256 + threadIdx.x;
    int v = (i < NTOT) ? g_cnt[i] : 0;
    if (i < NTOT) {
        float d = (float)v + 1.0f;
        g_dinv[i]   = rsqrtf(d);
        g_invdeg[i] = 1.0f / d;
    }
    sh[threadIdx.x] = v;
    __syncthreads();
    for (int o = 1; o < 256; o <<= 1) {
        int t = (threadIdx.x >= o) ? sh[threadIdx.x - o] : 0;
        __syncthreads();
        sh[threadIdx.x] += t;
        __syncthreads();
    }
    if (i < NTOT) g_start[i] = sh[threadIdx.x] - v;
    if (threadIdx.x == 255) g_bsum[blockIdx.x] = sh[255];
}

__global__ void scanB_kernel(int nb) {
    __shared__ int sh[1024];
    int i = threadIdx.x;
    int v = (i < nb) ? g_bsum[i] : 0;
    sh[i] = v;
    __syncthreads();
    for (int o = 1; o < 1024; o <<= 1) {
        int t = (i >= o) ? sh[i - o] : 0;
        __syncthreads();
        sh[i] += t;
        __syncthreads();
    }
    g_bsum[i] = sh[i] - v;
}

__global__ void scanC_kernel() {
    int i = blockIdx.x * 256 + threadIdx.x;
    if (i < NTOT) {
        int s = g_start[i] + g_bsum[blockIdx.x];
        g_start[i] = s;
        g_cursor[i] = s;
    }
    if (i == 0) g_start[NTOT] = ETOT;
}

__global__ void scatter_kernel(const int* __restrict__ adj) {
    int i = blockIdx.x * blockDim.x + threadIdx.x;
    if (i >= ETOT) return;
    int j = i / EDGES;
    int e = i - j * EDGES;
    int src = adj[(size_t)j * 2 * EDGES + e];
    int dst = adj[(size_t)j * 2 * EDGES + EDGES + e];
    int pos = atomicAdd(&g_cursor[j * NNODES + dst], 1);
    float w = g_dinv[j * NNODES + src] * g_dinv[j * NNODES + dst];
    g_edge[pos] = make_uint2((unsigned)src, __float_as_uint(w));
}

__global__ void pack_wc_h_kernel(const float* __restrict__ W_convs,
                                 const float* __restrict__ W_extra) {
    int i = blockIdx.x * blockDim.x + threadIdx.x;
    if (i >= FIN * NCAT) return;
    int k = i / NCAT;
    int c = i - k * NCAT;
    float v;
    if (c < 3 * HID) {
        int br = c / HID, h = c - br * HID;
        v = W_convs[(size_t)br * FIN * HID + (size_t)k * HID + h];
    } else {
        v = W_extra[(size_t)k * HID + (c - 3 * HID)];
    }
    g_Wch[i] = __float2half_rn(v);
}

__global__ void conv_h_kernel(const float* __restrict__ src,
                              __half* __restrict__ dst, int n) {
    int i = blockIdx.x * blockDim.x + threadIdx.x;
    if (i >= n) return;
    dst[i] = __float2half_rn(src[i]);
}

__global__ void pack_wc48_kernel(const float* __restrict__ W_cls) {
    int i = blockIdx.x * blockDim.x + threadIdx.x;
    if (i >= NCAT * CLSP) return;
    int k = i / CLSP;
    int n = i - k * CLSP;
    g_Wc48[i] = (n < NCLS) ? __float2half_rn(W_cls[(size_t)k * NCLS + n]) : __ushort_as_half(0);
}

// ---------------- MMA helpers ------------------------------------------------
__device__ __forceinline__ uint32_t smem_u32(const void* p) {
    return (uint32_t)__cvta_generic_to_shared(p);
}
__device__ __forceinline__ void ldsm_x4(uint32_t* r, uint32_t addr) {
    asm volatile("ldmatrix.sync.aligned.m8n8.x4.shared.b16 {%0,%1,%2,%3},[%4];"
                 : "=r"(r[0]), "=r"(r[1]), "=r"(r[2]), "=r"(r[3]) : "r"(addr));
}
__device__ __forceinline__ void ldsm_x4_t(uint32_t* r, uint32_t addr) {
    asm volatile("ldmatrix.sync.aligned.m8n8.x4.trans.shared.b16 {%0,%1,%2,%3},[%4];"
                 : "=r"(r[0]), "=r"(r[1]), "=r"(r[2]), "=r"(r[3]) : "r"(addr));
}
__device__ __forceinline__ void mma_f16(float* c, const uint32_t* a, const uint32_t* b) {
    asm volatile(
        "mma.sync.aligned.m16n8k16.row.col.f32.f16.f16.f32 "
        "{%0,%1,%2,%3},{%4,%5,%6,%7},{%8,%9},{%0,%1,%2,%3};"
        : "+f"(c[0]), "+f"(c[1]), "+f"(c[2]), "+f"(c[3])
        : "r"(a[0]), "r"(a[1]), "r"(a[2]), "r"(a[3]), "r"(b[0]), "r"(b[1]));
}
__device__ __forceinline__ void cp16(uint32_t dst, const void* src, bool valid) {
    int sz = valid ? 16 : 0;
    asm volatile("cp.async.cg.shared.global [%0],[%1],16,%2;"
                 :: "r"(dst), "l"(src), "r"(sz));
}

// ---------------- unified fp16 GEMM ------------------------------------------
#define AS_STRIDE 40
#define BS_STRIDE 136

__global__ __launch_bounds__(256, 2) void gemm_h_kernel(
    const __half* __restrict__ A, int lda,
    const __half* __restrict__ B, int ldb,
    __half* __restrict__ C, int ldc, int M, int K) {
    __shared__ __half As[3][128][AS_STRIDE];
    __shared__ __half Bs[3][32][BS_STRIDE];
    int tid = threadIdx.x, lane = tid & 31, wid = tid >> 5;
    int wm = wid & 3, wn = wid >> 2;
    int bm = blockIdx.y * 128, bn = blockIdx.x * 128;
    int nstages = K >> 5;

    int ar = tid >> 2, ac = (tid & 3) * 8;
    int br = tid >> 4, bc = (tid & 15) * 8;
    int r0 = bm + ar, r1 = bm + 64 + ar;
    bool v0 = r0 < M, v1 = r1 < M;
    int r0c = v0 ? r0 : 0, r1c = v1 ? r1 : 0;

    float c[2][8][4];
#pragma unroll
    for (int t = 0; t < 2; t++)
#pragma unroll
        for (int j = 0; j < 8; j++)
#pragma unroll
            for (int q = 0; q < 4; q++) c[t][j][q] = 0.f;

    uint32_t sA0[3], sA1[3], sB0[3], sB1[3];
#pragma unroll
    for (int b = 0; b < 3; b++) {
        sA0[b] = smem_u32(&As[b][ar][ac]);
        sA1[b] = smem_u32(&As[b][64 + ar][ac]);
        sB0[b] = smem_u32(&Bs[b][br][bc]);
        sB1[b] = smem_u32(&Bs[b][16 + br][bc]);
    }

#define GISSUE(stage, buf)                                                    \
    {                                                                         \
        int kk = (stage) * 32;                                                \
        cp16(sA0[buf], A + (size_t)r0c * lda + kk + ac, v0);                  \
        cp16(sA1[buf], A + (size_t)r1c * lda + kk + ac, v1);                  \
        cp16(sB0[buf], B + (size_t)(kk + br) * ldb + bn + bc, true);          \
        cp16(sB1[buf], B + (size_t)(kk + 16 + br) * ldb + bn + bc, true);     \
        asm volatile("cp.async.commit_group;");                               \
    }

    uint32_t aBase[3], bBase[3];
#pragma unroll
    for (int b = 0; b < 3; b++) {
        aBase[b] = smem_u32(&As[b][wm * 32 + (lane & 15)][(lane >> 4) * 8]);
        int bRow = (lane & 7) + ((lane >> 3) & 1) * 8;
        bBase[b] = smem_u32(&Bs[b][bRow][wn * 64 + (lane >> 4) * 8]);
    }

    GISSUE(0, 0);
    GISSUE(1, 1);
    int buf = 0;
    for (int s = 0; s < nstages; s++) {
        if (s + 2 < nstages) {
            GISSUE(s + 2, (buf + 2) % 3);
            asm volatile("cp.async.wait_group 2;");
        } else {
            asm volatile("cp.async.wait_group 0;");
        }
        __syncthreads();
#pragma unroll
        for (int ks = 0; ks < 2; ks++) {
            uint32_t a[2][4];
            uint32_t aAddr = aBase[buf] + ks * 16 * 2;
            ldsm_x4(a[0], aAddr);
            ldsm_x4(a[1], aAddr + 16 * AS_STRIDE * 2);
            uint32_t bf[4][4];
            uint32_t bAddr = bBase[buf] + ks * 16 * BS_STRIDE * 2;
#pragma unroll
            for (int j4 = 0; j4 < 4; j4++)
                ldsm_x4_t(bf[j4], bAddr + j4 * 16 * 2);
#pragma unroll
            for (int t = 0; t < 2; t++)
#pragma unroll
                for (int j = 0; j < 8; j++)
                    mma_f16(c[t][j], a[t], &bf[j >> 1][(j & 1) * 2]);
        }
        __syncthreads();
        buf = (buf + 1) % 3;
    }

    int r = lane >> 2, cc = (lane & 3) * 2;
#pragma unroll
    for (int t = 0; t < 2; t++) {
        int m0 = bm + wm * 32 + t * 16;
#pragma unroll
        for (int j = 0; j < 8; j++) {
            int n0 = bn + wn * 64 + j * 8;
            if (m0 + r < M)
                *(__half2*)(C + (size_t)(m0 + r) * ldc + n0 + cc) =
                    __floats2half2_rn(c[t][j][0], c[t][j][1]);
            if (m0 + r + 8 < M)
                *(__half2*)(C + (size_t)(m0 + r + 8) * ldc + n0 + cc) =
                    __floats2half2_rn(c[t][j][2], c[t][j][3]);
        }
    }
#undef GISSUE
}

// ---------------- CSR gather aggregation (packed edges, 4-edge unroll) -------
__device__ __forceinline__ void agg_body(
    const int* __restrict__ start,
    const float* __restrict__ invdeg,
    const __half* __restrict__ Hsrc, int ldH,
    __half* __restrict__ Out, int ldO,
    int mode, float maskv,
    const float* __restrict__ bias,
    const float* __restrict__ bns, const float* __restrict__ bnt,
    int n, int lane) {
    int h = lane * 8;

    float acc[8];
    {
        uint4 v = *(const uint4*)(Hsrc + (size_t)n * ldH + h);
        const __half2* hp = (const __half2*)&v;
        float idg = invdeg[n];
#pragma unroll
        for (int q = 0; q < 4; q++) {
            float2 f = __half22float2(hp[q]);
            acc[q * 2 + 0] = f.x * idg;
            acc[q * 2 + 1] = f.y * idg;
        }
    }

    int e = start[n], eend = start[n + 1];
    for (; e + 4 <= eend; e += 4) {
        uint2 e0 = g_edge[e], e1 = g_edge[e + 1], e2 = g_edge[e + 2], e3 = g_edge[e + 3];
        float w0 = __uint_as_float(e0.y), w1 = __uint_as_float(e1.y);
        float w2 = __uint_as_float(e2.y), w3 = __uint_as_float(e3.y);
        uint4 u0 = *(const uint4*)(Hsrc + (size_t)e0.x * ldH + h);
        uint4 u1 = *(const uint4*)(Hsrc + (size_t)e1.x * ldH + h);
        uint4 u2 = *(const uint4*)(Hsrc + (size_t)e2.x * ldH + h);
        uint4 u3 = *(const uint4*)(Hsrc + (size_t)e3.x * ldH + h);
        const __half2 *h0 = (const __half2*)&u0, *h1 = (const __half2*)&u1;
        const __half2 *h2 = (const __half2*)&u2, *h3 = (const __half2*)&u3;
#pragma unroll
        for (int q = 0; q < 4; q++) {
            float2 f0 = __half22float2(h0[q]);
            float2 f1 = __half22float2(h1[q]);
            float2 f2 = __half22float2(h2[q]);
            float2 f3 = __half22float2(h3[q]);
            acc[q * 2 + 0] += w0 * f0.x + w1 * f1.x + w2 * f2.x + w3 * f3.x;
            acc[q * 2 + 1] += w0 * f0.y + w1 * f1.y + w2 * f2.y + w3 * f3.y;
        }
    }
    for (; e < eend; e++) {
        uint2 ee = g_edge[e];
        float wA = __uint_as_float(ee.y);
        uint4 vA = *(const uint4*)(Hsrc + (size_t)ee.x * ldH + h);
        const __half2* hA = (const __half2*)&vA;
#pragma unroll
        for (int q = 0; q < 4; q++) {
            float2 fA = __half22float2(hA[q]);
            acc[q * 2 + 0] += wA * fA.x;
            acc[q * 2 + 1] += wA * fA.y;
        }
    }

    float4 b0 = *(const float4*)(bias + h);
    float4 b1 = *(const float4*)(bias + h + 4);
    float bb[8] = {b0.x, b0.y, b0.z, b0.w, b1.x, b1.y, b1.z, b1.w};
#pragma unroll
    for (int q = 0; q < 8; q++) acc[q] += bb[q];
    if (mode != 0) {
        float4 sc0 = *(const float4*)(bns + h);
        float4 sc1 = *(const float4*)(bns + h + 4);
        float4 t0 = *(const float4*)(bnt + h);
        float4 t1 = *(const float4*)(bnt + h + 4);
        float ss[8] = {sc0.x, sc0.y, sc0.z, sc0.w, sc1.x, sc1.y, sc1.z, sc1.w};
        float tt[8] = {t0.x, t0.y, t0.z, t0.w, t1.x, t1.y, t1.z, t1.w};
#pragma unroll
        for (int q = 0; q < 8; q++) acc[q] = acc[q] * ss[q] + tt[q];
    }
#pragma unroll
    for (int q = 0; q < 8; q++) acc[q] = fmaxf(acc[q], 0.f) * maskv;

    uint4 o;
    __half2* oh = (__half2*)&o;
#pragma unroll
    for (int q = 0; q < 4; q++)
        oh[q] = __floats2half2_rn(acc[q * 2 + 0], acc[q * 2 + 1]);
    *(uint4*)(Out + (size_t)n * ldO + h) = o;
}

__global__ __launch_bounds__(256) void agg_conv3_kernel(const float* __restrict__ b_convs) {
    int warp = (blockIdx.x * blockDim.x + threadIdx.x) >> 5;
    int lane = threadIdx.x & 31;
    if (warp >= NNODES) return;
    int s = blockIdx.y;
    int a = s + 1;
    agg_body(g_start + a * NNODES, g_invdeg + a * NNODES,
             g_T1h + s * HID, NCAT,
             g_AGGh + s * HID, NCAT,
             0, g_mask[s], b_convs + s * HID, nullptr, nullptr,
             warp, lane);
}

__global__ __launch_bounds__(256) void agg_extra_kernel(
    const __half* __restrict__ Hsrc, __half* __restrict__ Out,
    int mode, int midx,
    const float* __restrict__ bias,
    const float* __restrict__ bns, const float* __restrict__ bnt) {
    int warp = (blockIdx.x * blockDim.x + threadIdx.x) >> 5;
    int lane = threadIdx.x & 31;
    if (warp >= NNODES) return;
    float maskv = (midx >= 0) ? g_mask[midx] : 1.0f;
    agg_body(g_start, g_invdeg, Hsrc, NCAT, Out, NCAT,
             mode, maskv, bias, bns, bnt, warp, lane);
}

// ---------------- classifier: split-K tensor-core + log_softmax --------------
#define CAS_STRIDE 72
template<int KBASE, int NCH, bool FINAL>
__global__ __launch_bounds__(256, 2) void cls_split_kernel(
    const __half* __restrict__ A,
    const float* __restrict__ b_cls,
    float* __restrict__ out, int M) {
    __shared__ __half As[2][128][CAS_STRIDE];
    __shared__ __half Ws[2][64][CLSP];
    int tid = threadIdx.x, lane = tid & 31, wm = tid >> 5;
    int bm = blockIdx.x * 128;

    float c[6][4];
#pragma unroll
    for (int j = 0; j < 6; j++)
#pragma unroll
        for (int q = 0; q < 4; q++) c[j][q] = 0.f;

    uint32_t sA[2][4], sW[2][2];
    int arow[4], acol[4];
#pragma unroll
    for (int t = 0; t < 4; t++) {
        int q = tid + t * 256;
        arow[t] = q >> 3;
        acol[t] = (q & 7) * 8;
#pragma unroll
        for (int b = 0; b < 2; b++) sA[b][t] = smem_u32(&As[b][arow[t]][acol[t]]);
    }
    int wrow[2] = {-1, -1}, wcol[2] = {0, 0};
#pragma unroll
    for (int t = 0; t < 2; t++) {
        int q = tid + t * 256;
        if (q < 384) { wrow[t] = q / 6; wcol[t] = (q % 6) * 8; }
#pragma unroll
        for (int b = 0; b < 2; b++)
            sW[b][t] = smem_u32(&Ws[b][wrow[t] < 0 ? 0 : wrow[t]][wcol[t]]);
    }

#define CISSUE(stage, buf)                                                    \
    {                                                                         \
        int k0 = KBASE + (stage) * 64;                                        \
        _Pragma("unroll")                                                     \
        for (int t = 0; t < 4; t++) {                                         \
            int gr = bm + arow[t];                                            \
            bool ok = gr < M;                                                 \
            cp16(sA[buf][t], A + (size_t)(ok ? gr : 0) * NCAT + k0 + acol[t], ok); \
        }                                                                     \
        _Pragma("unroll")                                                     \
        for (int t = 0; t < 2; t++)                                           \
            if (wrow[t] >= 0)                                                 \
                cp16(sW[buf][t], g_Wc48 + (size_t)(k0 + wrow[t]) * CLSP + wcol[t], true); \
        asm volatile("cp.async.commit_group;");                               \
    }

    uint32_t aBase[2], wBase[2];
    int bRow = (lane & 7) + ((lane >> 3) & 1) * 8;
#pragma unroll
    for (int b = 0; b < 2; b++) {
        aBase[b] = smem_u32(&As[b][wm * 16 + (lane & 15)][(lane >> 4) * 8]);
        wBase[b] = smem_u32(&Ws[b][bRow][(lane >> 4) * 8]);
    }

    CISSUE(0, 0);
    for (int s = 0; s < NCH; s++) {
        int buf = s & 1;
        if (s + 1 < NCH) {
            CISSUE(s + 1, buf ^ 1);
            asm volatile("cp.async.wait_group 1;");
        } else {
            asm volatile("cp.async.wait_group 0;");
        }
        __syncthreads();
#pragma unroll
        for (int ks = 0; ks < 4; ks++) {
            uint32_t a[4];
            ldsm_x4(a, aBase[buf] + ks * 16 * 2);
            uint32_t bf[3][4];
#pragma unroll
            for (int j16 = 0; j16 < 3; j16++)
                ldsm_x4_t(bf[j16], wBase[buf] + (ks * 16 * CLSP + j16 * 16) * 2);
#pragma unroll
            for (int j = 0; j < 6; j++)
                mma_f16(c[j], a, &bf[j >> 1][(j & 1) * 2]);
        }
        __syncthreads();
    }

    size_t pbase = ((size_t)blockIdx.x * 256 + tid) * 24;
    if (!FINAL) {
#pragma unroll
        for (int j = 0; j < 6; j++)
            *(float4*)(g_part + pbase + j * 4) = make_float4(c[j][0], c[j][1], c[j][2], c[j][3]);
        return;
    }

#pragma unroll
    for (int j = 0; j < 6; j++) {
        float4 p = *(const float4*)(g_part + pbase + j * 4);
        c[j][0] += p.x; c[j][1] += p.y; c[j][2] += p.z; c[j][3] += p.w;
    }
    int r = lane >> 2, q = lane & 3;
    int row0 = bm + wm * 16 + r, row1 = row0 + 8;
    float v0[10], v1[10];
#pragma unroll
    for (int j = 0; j < 5; j++) {
        int col = j * 8 + q * 2;
        float bq0 = b_cls[col], bq1 = b_cls[col + 1];
        v0[j * 2 + 0] = c[j][0] + bq0;
        v0[j * 2 + 1] = c[j][1] + bq1;
        v1[j * 2 + 0] = c[j][2] + bq0;
        v1[j * 2 + 1] = c[j][3] + bq1;
    }
    float m0 = -1e30f, m1 = -1e30f;
#pragma unroll
    for (int i = 0; i < 10; i++) { m0 = fmaxf(m0, v0[i]); m1 = fmaxf(m1, v1[i]); }
#pragma unroll
    for (int o = 1; o <= 2; o <<= 1) {
        m0 = fmaxf(m0, __shfl_xor_sync(0xffffffffu, m0, o));
        m1 = fmaxf(m1, __shfl_xor_sync(0xffffffffu, m1, o));
    }
    float s0 = 0.f, s1 = 0.f;
#pragma unroll
    for (int i = 0; i < 10; i++) { s0 += expf(v0[i] - m0); s1 += expf(v1[i] - m1); }
#pragma unroll
    for (int o = 1; o <= 2; o <<= 1) {
        s0 += __shfl_xor_sync(0xffffffffu, s0, o);
        s1 += __shfl_xor_sync(0xffffffffu, s1, o);
    }
    float L0 = m0 + logf(s0), L1 = m1 + logf(s1);
    if (row0 < M) {
#pragma unroll
        for (int j = 0; j < 5; j++) {
            int col = j * 8 + q * 2;
            out[(size_t)row0 * NCLS + col]     = v0[j * 2 + 0] - L0;
            out[(size_t)row0 * NCLS + col + 1] = v0[j * 2 + 1] - L0;
        }
    }
    if (row1 < M) {
#pragma unroll
        for (int j = 0; j < 5; j++) {
            int col = j * 8 + q * 2;
            out[(size_t)row1 * NCLS + col]     = v1[j * 2 + 0] - L1;
            out[(size_t)row1 * NCLS + col + 1] = v1[j * 2 + 1] - L1;
        }
    }
#undef CISSUE
}

__global__ void tail_kernel(float* out, int startI, int total) {
    int i = startI + blockIdx.x * blockDim.x + threadIdx.x;
    if (i < total) out[i] = 0.f;
}

// ---------------- launch ----------------------------------------------------
extern "C" void kernel_launch(void* const* d_in, const int* in_sizes, int n_in,
                              void* d_out, int out_size) {
    const float* x        = (const float*)d_in[0];
    const int*   adj      = (const int*)d_in[1];
    const float* W_convs  = (const float*)d_in[2];
    const float* b_convs  = (const float*)d_in[3];
    const float* W_extra  = (const float*)d_in[4];
    const float* b_extra  = (const float*)d_in[5];
    const float* bn1g     = (const float*)d_in[6];
    const float* bn1b     = (const float*)d_in[7];
    const float* bn1m     = (const float*)d_in[8];
    const float* bn1v     = (const float*)d_in[9];
    const float* W_extra2 = (const float*)d_in[10];
    const float* b_extra2 = (const float*)d_in[11];
    const float* bn2g     = (const float*)d_in[12];
    const float* bn2b     = (const float*)d_in[13];
    const float* bn2m     = (const float*)d_in[14];
    const float* bn2v     = (const float*)d_in[15];
    const float* att      = (const float*)d_in[16];
    const float* W_cls    = (const float*)d_in[17];
    const float* b_cls    = (const float*)d_in[18];
    float* out = (float*)d_out;

    float *p_bn1s, *p_bn1t, *p_bn2s, *p_bn2t;
    __half *p_T1h, *p_AGGh, *p_xh, *p_Wch, *p_W2h;
    cudaGetSymbolAddress((void**)&p_T1h,   g_T1h);
    cudaGetSymbolAddress((void**)&p_AGGh,  g_AGGh);
    cudaGetSymbolAddress((void**)&p_bn1s,  g_bn1s);
    cudaGetSymbolAddress((void**)&p_bn1t,  g_bn1t);
    cudaGetSymbolAddress((void**)&p_bn2s,  g_bn2s);
    cudaGetSymbolAddress((void**)&p_bn2t,  g_bn2t);
    cudaGetSymbolAddress((void**)&p_xh,    g_xh);
    cudaGetSymbolAddress((void**)&p_Wch,   g_Wch);
    cudaGetSymbolAddress((void**)&p_W2h,   g_W2h);

    static cudaStream_t s1 = nullptr, s2 = nullptr;
    static cudaEvent_t evRoot = nullptr, evCSR = nullptr, evT1s3 = nullptr, evExtra = nullptr;
    if (s1 == nullptr) {
        int pLo, pHi;
        cudaDeviceGetStreamPriorityRange(&pLo, &pHi);
        cudaStreamCreateWithFlags(&s1, cudaStreamNonBlocking);
        cudaStreamCreateWithPriority(&s2, cudaStreamNonBlocking, pHi);
        cudaEventCreateWithFlags(&evRoot,  cudaEventDisableTiming);
        cudaEventCreateWithFlags(&evCSR,   cudaEventDisableTiming);
        cudaEventCreateWithFlags(&evT1s3,  cudaEventDisableTiming);
        cudaEventCreateWithFlags(&evExtra, cudaEventDisableTiming);
    }

    const int SCAN_BLOCKS = (NTOT + 255) / 256;
    const int agg_blocks = (NNODES * 32 + 255) / 256;
    const int mrows = (NNODES + 127) / 128;

    // ======== fork 1: CSR build + off-path weight packs on s1 =================
    cudaEventRecord(evRoot, 0);
    cudaStreamWaitEvent(s1, evRoot, 0);

    zero_cnt_kernel<<<SCAN_BLOCKS, 256, 0, s1>>>();
    count_deg_kernel<<<(ETOT + 255) / 256, 256, 0, s1>>>(adj);
    scanA_kernel<<<SCAN_BLOCKS, 256, 0, s1>>>();
    scanB_kernel<<<1, 1024, 0, s1>>>(SCAN_BLOCKS);
    scanC_kernel<<<SCAN_BLOCKS, 256, 0, s1>>>();
    scatter_kernel<<<(ETOT + 255) / 256, 256, 0, s1>>>(adj);
    conv_h_kernel<<<(HID * HID + 255) / 256, 256, 0, s1>>>(W_extra2, p_W2h, HID * HID);
    pack_wc48_kernel<<<(NCAT * CLSP + 255) / 256, 256, 0, s1>>>(W_cls);
    cudaEventRecord(evCSR, s1);

    // ======== default: minimal prep then GEMM1 slice3 first ===================
    params_kernel<<<1, 256>>>(att, bn1g, bn1b, bn1m, bn1v, bn2g, bn2b, bn2m, bn2v);
    pack_wc_h_kernel<<<(FIN * NCAT + 255) / 256, 256>>>(W_convs, W_extra);
    conv_h_kernel<<<(NNODES * FIN + 255) / 256, 256>>>(x, p_xh, NNODES * FIN);

    // GEMM1 slice 3 (cols 768..1023) — unblocks the extra branch
    {
        dim3 grid(2, mrows);
        gemm_h_kernel<<<grid, 256>>>(p_xh, FIN, p_Wch + 768, NCAT,
                                     p_T1h + 768, NCAT, NNODES, FIN);
    }
    cudaEventRecord(evT1s3, 0);
    // GEMM1 slices 0..2 (cols 0..767)
    {
        dim3 grid(6, mrows);
        gemm_h_kernel<<<grid, 256>>>(p_xh, FIN, p_Wch, NCAT,
                                     p_T1h, NCAT, NNODES, FIN);
    }
    cudaStreamWaitEvent(0, evCSR, 0);     // conv aggs need CSR

    // ======== fork 2: extra branch on s2 (high priority, critical path) =======
    cudaStreamWaitEvent(s2, evT1s3, 0);
    cudaStreamWaitEvent(s2, evCSR, 0);

    agg_extra_kernel<<<agg_blocks, 256, 0, s2>>>(
        p_T1h + 3 * HID, p_AGGh + 3 * HID, 1, -1, b_extra, p_bn1s, p_bn1t);
    {
        dim3 grid(HID / 128, mrows);
        gemm_h_kernel<<<grid, 256, 0, s2>>>(p_AGGh + 3 * HID, NCAT,
                                            p_W2h, HID,
                                            p_T1h + 3 * HID, NCAT, NNODES, HID);
    }
    agg_extra_kernel<<<agg_blocks, 256, 0, s2>>>(
        p_T1h + 3 * HID, p_AGGh + 3 * HID, 2, 3, b_extra2, p_bn2s, p_bn2t);
    cudaEventRecord(evExtra, s2);

    // ======== default: conv aggs + partial classifier (K=768) =================
    {
        dim3 grid(agg_blocks, 3);
        agg_conv3_kernel<<<grid, 256>>>(b_convs);
    }
    cls_split_kernel<0, 12, false><<<CLS_BLOCKS, 256>>>(p_AGGh, b_cls, out, NNODES);
    cudaStreamWaitEvent(0, evExtra, 0);

    // ======== final classifier slice (K=256) + log_softmax ====================
    cls_split_kernel<768, 4, true><<<CLS_BLOCKS, 256>>>(p_AGGh, b_cls, out, NNODES);
    int tail = out_size - NNODES * NCLS;
    if (tail > 0)
        tail_kernel<<<(tail + 255) / 256, 256>>>(out, NNODES * NCLS, out_size);
}

// round 15
// speedup vs baseline: 1.0770x; 1.0770x over previous
#include <cuda_runtime.h>
#include <cuda_fp16.h>
#include <cstdint>

#define NNODES 50000
#define EDGES 800000
#define FIN 256
#define HID 256
#define NCAT 1024
#define NCLS 40
#define CLSP 48
#define BN_EPS 1e-5f
#define NTOT (4 * NNODES)
#define ETOT (4 * EDGES)
#define CLS_BLOCKS ((NNODES + 127) / 128)

// ---------------- scratch (static device globals) ---------------------------
__device__ __half g_T1h[(size_t)NNODES * NCAT];
__device__ __half g_AGGh[(size_t)NNODES * NCAT];
__device__ int   g_cnt[NTOT];
__device__ float g_dinv[NTOT];
__device__ float g_invdeg[NTOT];
__device__ int   g_start[NTOT + 1];
__device__ int   g_cursor[NTOT];
__device__ int   g_bsum[1024];
__device__ int   g_esrc[ETOT];
__device__ float g_ew[ETOT];
__device__ float g_mask[4];
__device__ float g_bn1s[HID], g_bn1t[HID], g_bn2s[HID], g_bn2t[HID];
__device__ __half g_xh[(size_t)NNODES * FIN];
__device__ __half g_Wch[FIN * NCAT];
__device__ __half g_W2h[HID * HID];
__device__ __half g_Wc48[NCAT * CLSP];
__device__ float g_part[(size_t)CLS_BLOCKS * 256 * 24];

// ---------------- tiny prep kernels -----------------------------------------
__global__ void params_kernel(const float* __restrict__ att,
                              const float* g1, const float* b1, const float* m1, const float* v1,
                              const float* g2, const float* b2, const float* m2, const float* v2) {
    int i = threadIdx.x;
    if (i < HID) {
        float s1 = g1[i] * rsqrtf(v1[i] + BN_EPS);
        g_bn1s[i] = s1; g_bn1t[i] = b1[i] - m1[i] * s1;
        float s2 = g2[i] * rsqrtf(v2[i] + BN_EPS);
        g_bn2s[i] = s2; g_bn2t[i] = b2[i] - m2[i] * s2;
    }
    if (i == 0) {
        float m = att[0];
        for (int k = 1; k < 4; k++) m = fmaxf(m, att[k]);
        float s = 0.f, e[4];
        for (int k = 0; k < 4; k++) { e[k] = expf(att[k] - m); s += e[k]; }
        for (int k = 0; k < 4; k++) g_mask[k] = e[k] / s;
    }
}

__global__ void zero_cnt_kernel() {
    int i = blockIdx.x * blockDim.x + threadIdx.x;
    if (i < NTOT) g_cnt[i] = 0;
}

__global__ void count_deg_kernel(const int* __restrict__ adj) {
    int i = blockIdx.x * blockDim.x + threadIdx.x;
    if (i >= ETOT) return;
    int j = i / EDGES;
    int e = i - j * EDGES;
    int dst = adj[(size_t)j * 2 * EDGES + EDGES + e];
    atomicAdd(&g_cnt[j * NNODES + dst], 1);
}

__global__ void scanA_kernel() {
    __shared__ int sh[256];
    int i = blockIdx.x * 256 + threadIdx.x;
    int v = (i < NTOT) ? g_cnt[i] : 0;
    if (i < NTOT) {
        float d = (float)v + 1.0f;
        g_dinv[i]   = rsqrtf(d);
        g_invdeg[i] = 1.0f / d;
    }
    sh[threadIdx.x] = v;
    __syncthreads();
    for (int o = 1; o < 256; o <<= 1) {
        int t = (threadIdx.x >= o) ? sh[threadIdx.x - o] : 0;
        __syncthreads();
        sh[threadIdx.x] += t;
        __syncthreads();
    }
    if (i < NTOT) g_start[i] = sh[threadIdx.x] - v;
    if (threadIdx.x == 255) g_bsum[blockIdx.x] = sh[255];
}

__global__ void scanB_kernel(int nb) {
    __shared__ int sh[1024];
    int i = threadIdx.x;
    int v = (i < nb) ? g_bsum[i] : 0;
    sh[i] = v;
    __syncthreads();
    for (int o = 1; o < 1024; o <<= 1) {
        int t = (i >= o) ? sh[i - o] : 0;
        __syncthreads();
        sh[i] += t;
        __syncthreads();
    }
    g_bsum[i] = sh[i] - v;
}

__global__ void scanC_kernel() {
    int i = blockIdx.x * 256 + threadIdx.x;
    if (i < NTOT) {
        int s = g_start[i] + g_bsum[blockIdx.x];
        g_start[i] = s;
        g_cursor[i] = s;
    }
    if (i == 0) g_start[NTOT] = ETOT;
}

__global__ void scatter_kernel(const int* __restrict__ adj) {
    int i = blockIdx.x * blockDim.x + threadIdx.x;
    if (i >= ETOT) return;
    int j = i / EDGES;
    int e = i - j * EDGES;
    int src = adj[(size_t)j * 2 * EDGES + e];
    int dst = adj[(size_t)j * 2 * EDGES + EDGES + e];
    int pos = atomicAdd(&g_cursor[j * NNODES + dst], 1);
    g_esrc[pos] = src;
    g_ew[pos] = g_dinv[j * NNODES + src] * g_dinv[j * NNODES + dst];
}

__global__ void pack_wc_h_kernel(const float* __restrict__ W_convs,
                                 const float* __restrict__ W_extra) {
    int i = blockIdx.x * blockDim.x + threadIdx.x;
    if (i >= FIN * NCAT) return;
    int k = i / NCAT;
    int c = i - k * NCAT;
    float v;
    if (c < 3 * HID) {
        int br = c / HID, h = c - br * HID;
        v = W_convs[(size_t)br * FIN * HID + (size_t)k * HID + h];
    } else {
        v = W_extra[(size_t)k * HID + (c - 3 * HID)];
    }
    g_Wch[i] = __float2half_rn(v);
}

__global__ void conv_h_kernel(const float* __restrict__ src,
                              __half* __restrict__ dst, int n) {
    int i = blockIdx.x * blockDim.x + threadIdx.x;
    if (i >= n) return;
    dst[i] = __float2half_rn(src[i]);
}

__global__ void pack_wc48_kernel(const float* __restrict__ W_cls) {
    int i = blockIdx.x * blockDim.x + threadIdx.x;
    if (i >= NCAT * CLSP) return;
    int k = i / CLSP;
    int n = i - k * CLSP;
    g_Wc48[i] = (n < NCLS) ? __float2half_rn(W_cls[(size_t)k * NCLS + n]) : __ushort_as_half(0);
}

// ---------------- MMA helpers ------------------------------------------------
__device__ __forceinline__ uint32_t smem_u32(const void* p) {
    return (uint32_t)__cvta_generic_to_shared(p);
}
__device__ __forceinline__ void ldsm_x4(uint32_t* r, uint32_t addr) {
    asm volatile("ldmatrix.sync.aligned.m8n8.x4.shared.b16 {%0,%1,%2,%3},[%4];"
                 : "=r"(r[0]), "=r"(r[1]), "=r"(r[2]), "=r"(r[3]) : "r"(addr));
}
__device__ __forceinline__ void ldsm_x4_t(uint32_t* r, uint32_t addr) {
    asm volatile("ldmatrix.sync.aligned.m8n8.x4.trans.shared.b16 {%0,%1,%2,%3},[%4];"
                 : "=r"(r[0]), "=r"(r[1]), "=r"(r[2]), "=r"(r[3]) : "r"(addr));
}
__device__ __forceinline__ void mma_f16(float* c, const uint32_t* a, const uint32_t* b) {
    asm volatile(
        "mma.sync.aligned.m16n8k16.row.col.f32.f16.f16.f32 "
        "{%0,%1,%2,%3},{%4,%5,%6,%7},{%8,%9},{%0,%1,%2,%3};"
        : "+f"(c[0]), "+f"(c[1]), "+f"(c[2]), "+f"(c[3])
        : "r"(a[0]), "r"(a[1]), "r"(a[2]), "r"(a[3]), "r"(b[0]), "r"(b[1]));
}
__device__ __forceinline__ void cp16(uint32_t dst, const void* src, bool valid) {
    int sz = valid ? 16 : 0;
    asm volatile("cp.async.cg.shared.global [%0],[%1],16,%2;"
                 :: "r"(dst), "l"(src), "r"(sz));
}

// ---------------- unified fp16 GEMM ------------------------------------------
#define AS_STRIDE 40
#define BS_STRIDE 136

__global__ __launch_bounds__(256, 2) void gemm_h_kernel(
    const __half* __restrict__ A, int lda,
    const __half* __restrict__ B, int ldb,
    __half* __restrict__ C, int ldc, int M, int K) {
    __shared__ __half As[3][128][AS_STRIDE];
    __shared__ __half Bs[3][32][BS_STRIDE];
    int tid = threadIdx.x, lane = tid & 31, wid = tid >> 5;
    int wm = wid & 3, wn = wid >> 2;
    int bm = blockIdx.y * 128, bn = blockIdx.x * 128;
    int nstages = K >> 5;

    int ar = tid >> 2, ac = (tid & 3) * 8;
    int br = tid >> 4, bc = (tid & 15) * 8;
    int r0 = bm + ar, r1 = bm + 64 + ar;
    bool v0 = r0 < M, v1 = r1 < M;
    int r0c = v0 ? r0 : 0, r1c = v1 ? r1 : 0;

    float c[2][8][4];
#pragma unroll
    for (int t = 0; t < 2; t++)
#pragma unroll
        for (int j = 0; j < 8; j++)
#pragma unroll
            for (int q = 0; q < 4; q++) c[t][j][q] = 0.f;

    uint32_t sA0[3], sA1[3], sB0[3], sB1[3];
#pragma unroll
    for (int b = 0; b < 3; b++) {
        sA0[b] = smem_u32(&As[b][ar][ac]);
        sA1[b] = smem_u32(&As[b][64 + ar][ac]);
        sB0[b] = smem_u32(&Bs[b][br][bc]);
        sB1[b] = smem_u32(&Bs[b][16 + br][bc]);
    }

#define GISSUE(stage, buf)                                                    \
    {                                                                         \
        int kk = (stage) * 32;                                                \
        cp16(sA0[buf], A + (size_t)r0c * lda + kk + ac, v0);                  \
        cp16(sA1[buf], A + (size_t)r1c * lda + kk + ac, v1);                  \
        cp16(sB0[buf], B + (size_t)(kk + br) * ldb + bn + bc, true);          \
        cp16(sB1[buf], B + (size_t)(kk + 16 + br) * ldb + bn + bc, true);     \
        asm volatile("cp.async.commit_group;");                               \
    }

    uint32_t aBase[3], bBase[3];
#pragma unroll
    for (int b = 0; b < 3; b++) {
        aBase[b] = smem_u32(&As[b][wm * 32 + (lane & 15)][(lane >> 4) * 8]);
        int bRow = (lane & 7) + ((lane >> 3) & 1) * 8;
        bBase[b] = smem_u32(&Bs[b][bRow][wn * 64 + (lane >> 4) * 8]);
    }

    GISSUE(0, 0);
    GISSUE(1, 1);
    int buf = 0;
    for (int s = 0; s < nstages; s++) {
        if (s + 2 < nstages) {
            GISSUE(s + 2, (buf + 2) % 3);
            asm volatile("cp.async.wait_group 2;");
        } else {
            asm volatile("cp.async.wait_group 0;");
        }
        __syncthreads();
#pragma unroll
        for (int ks = 0; ks < 2; ks++) {
            uint32_t a[2][4];
            uint32_t aAddr = aBase[buf] + ks * 16 * 2;
            ldsm_x4(a[0], aAddr);
            ldsm_x4(a[1], aAddr + 16 * AS_STRIDE * 2);
            uint32_t bf[4][4];
            uint32_t bAddr = bBase[buf] + ks * 16 * BS_STRIDE * 2;
#pragma unroll
            for (int j4 = 0; j4 < 4; j4++)
                ldsm_x4_t(bf[j4], bAddr + j4 * 16 * 2);
#pragma unroll
            for (int t = 0; t < 2; t++)
#pragma unroll
                for (int j = 0; j < 8; j++)
                    mma_f16(c[t][j], a[t], &bf[j >> 1][(j & 1) * 2]);
        }
        __syncthreads();
        buf = (buf + 1) % 3;
    }

    int r = lane >> 2, cc = (lane & 3) * 2;
#pragma unroll
    for (int t = 0; t < 2; t++) {
        int m0 = bm + wm * 32 + t * 16;
#pragma unroll
        for (int j = 0; j < 8; j++) {
            int n0 = bn + wn * 64 + j * 8;
            if (m0 + r < M)
                *(__half2*)(C + (size_t)(m0 + r) * ldc + n0 + cc) =
                    __floats2half2_rn(c[t][j][0], c[t][j][1]);
            if (m0 + r + 8 < M)
                *(__half2*)(C + (size_t)(m0 + r + 8) * ldc + n0 + cc) =
                    __floats2half2_rn(c[t][j][2], c[t][j][3]);
        }
    }
#undef GISSUE
}

// ---------------- CSR gather aggregation (fp16, 8-edge unroll for MLP) -------
__device__ __forceinline__ void agg_body(
    const int* __restrict__ start,
    const float* __restrict__ invdeg,
    const __half* __restrict__ Hsrc, int ldH,
    __half* __restrict__ Out, int ldO,
    int mode, float maskv,
    const float* __restrict__ bias,
    const float* __restrict__ bns, const float* __restrict__ bnt,
    int n, int lane) {
    int h = lane * 8;

    float acc[8];
    {
        uint4 v = *(const uint4*)(Hsrc + (size_t)n * ldH + h);
        const __half2* hp = (const __half2*)&v;
        float idg = invdeg[n];
#pragma unroll
        for (int q = 0; q < 4; q++) {
            float2 f = __half22float2(hp[q]);
            acc[q * 2 + 0] = f.x * idg;
            acc[q * 2 + 1] = f.y * idg;
        }
    }

    int e = start[n], eend = start[n + 1];
    // 8-edge unroll: 8 outstanding 512B gathers per warp iteration
    for (; e + 8 <= eend; e += 8) {
        int si[8]; float w[8]; uint4 u[8];
#pragma unroll
        for (int t = 0; t < 8; t++) { si[t] = g_esrc[e + t]; w[t] = g_ew[e + t]; }
#pragma unroll
        for (int t = 0; t < 8; t++)
            u[t] = *(const uint4*)(Hsrc + (size_t)si[t] * ldH + h);
#pragma unroll
        for (int t = 0; t < 8; t++) {
            const __half2* hp = (const __half2*)&u[t];
#pragma unroll
            for (int q = 0; q < 4; q++) {
                float2 f = __half22float2(hp[q]);
                acc[q * 2 + 0] += w[t] * f.x;
                acc[q * 2 + 1] += w[t] * f.y;
            }
        }
    }
    for (; e + 2 <= eend; e += 2) {
        int sA = g_esrc[e], sB = g_esrc[e + 1];
        float wA = g_ew[e], wB = g_ew[e + 1];
        uint4 vA = *(const uint4*)(Hsrc + (size_t)sA * ldH + h);
        uint4 vB = *(const uint4*)(Hsrc + (size_t)sB * ldH + h);
        const __half2* hA = (const __half2*)&vA;
        const __half2* hB = (const __half2*)&vB;
#pragma unroll
        for (int q = 0; q < 4; q++) {
            float2 fA = __half22float2(hA[q]);
            float2 fB = __half22float2(hB[q]);
            acc[q * 2 + 0] += wA * fA.x + wB * fB.x;
            acc[q * 2 + 1] += wA * fA.y + wB * fB.y;
        }
    }
    if (e < eend) {
        int sA = g_esrc[e];
        float wA = g_ew[e];
        uint4 vA = *(const uint4*)(Hsrc + (size_t)sA * ldH + h);
        const __half2* hA = (const __half2*)&vA;
#pragma unroll
        for (int q = 0; q < 4; q++) {
            float2 fA = __half22float2(hA[q]);
            acc[q * 2 + 0] += wA * fA.x;
            acc[q * 2 + 1] += wA * fA.y;
        }
    }

    float4 b0 = *(const float4*)(bias + h);
    float4 b1 = *(const float4*)(bias + h + 4);
    float bb[8] = {b0.x, b0.y, b0.z, b0.w, b1.x, b1.y, b1.z, b1.w};
#pragma unroll
    for (int q = 0; q < 8; q++) acc[q] += bb[q];
    if (mode != 0) {
        float4 sc0 = *(const float4*)(bns + h);
        float4 sc1 = *(const float4*)(bns + h + 4);
        float4 t0 = *(const float4*)(bnt + h);
        float4 t1 = *(const float4*)(bnt + h + 4);
        float ss[8] = {sc0.x, sc0.y, sc0.z, sc0.w, sc1.x, sc1.y, sc1.z, sc1.w};
        float tt[8] = {t0.x, t0.y, t0.z, t0.w, t1.x, t1.y, t1.z, t1.w};
#pragma unroll
        for (int q = 0; q < 8; q++) acc[q] = acc[q] * ss[q] + tt[q];
    }
#pragma unroll
    for (int q = 0; q < 8; q++) acc[q] = fmaxf(acc[q], 0.f) * maskv;

    uint4 o;
    __half2* oh = (__half2*)&o;
#pragma unroll
    for (int q = 0; q < 4; q++)
        oh[q] = __floats2half2_rn(acc[q * 2 + 0], acc[q * 2 + 1]);
    *(uint4*)(Out + (size_t)n * ldO + h) = o;
}

__global__ __launch_bounds__(256) void agg_conv3_kernel(const float* __restrict__ b_convs) {
    int warp = (blockIdx.x * blockDim.x + threadIdx.x) >> 5;
    int lane = threadIdx.x & 31;
    if (warp >= NNODES) return;
    int s = blockIdx.y;
    int a = s + 1;
    agg_body(g_start + a * NNODES, g_invdeg + a * NNODES,
             g_T1h + s * HID, NCAT,
             g_AGGh + s * HID, NCAT,
             0, g_mask[s], b_convs + s * HID, nullptr, nullptr,
             warp, lane);
}

__global__ __launch_bounds__(256) void agg_extra_kernel(
    const __half* __restrict__ Hsrc, __half* __restrict__ Out,
    int mode, int midx,
    const float* __restrict__ bias,
    const float* __restrict__ bns, const float* __restrict__ bnt) {
    int warp = (blockIdx.x * blockDim.x + threadIdx.x) >> 5;
    int lane = threadIdx.x & 31;
    if (warp >= NNODES) return;
    float maskv = (midx >= 0) ? g_mask[midx] : 1.0f;
    agg_body(g_start, g_invdeg, Hsrc, NCAT, Out, NCAT,
             mode, maskv, bias, bns, bnt, warp, lane);
}

// ---------------- classifier: split-K tensor-core + log_softmax --------------
#define CAS_STRIDE 72
template<int KBASE, int NCH, bool FINAL>
__global__ __launch_bounds__(256, 2) void cls_split_kernel(
    const __half* __restrict__ A,
    const float* __restrict__ b_cls,
    float* __restrict__ out, int M) {
    __shared__ __half As[2][128][CAS_STRIDE];
    __shared__ __half Ws[2][64][CLSP];
    int tid = threadIdx.x, lane = tid & 31, wm = tid >> 5;
    int bm = blockIdx.x * 128;

    float c[6][4];
#pragma unroll
    for (int j = 0; j < 6; j++)
#pragma unroll
        for (int q = 0; q < 4; q++) c[j][q] = 0.f;

    uint32_t sA[2][4], sW[2][2];
    int arow[4], acol[4];
#pragma unroll
    for (int t = 0; t < 4; t++) {
        int q = tid + t * 256;
        arow[t] = q >> 3;
        acol[t] = (q & 7) * 8;
#pragma unroll
        for (int b = 0; b < 2; b++) sA[b][t] = smem_u32(&As[b][arow[t]][acol[t]]);
    }
    int wrow[2] = {-1, -1}, wcol[2] = {0, 0};
#pragma unroll
    for (int t = 0; t < 2; t++) {
        int q = tid + t * 256;
        if (q < 384) { wrow[t] = q / 6; wcol[t] = (q % 6) * 8; }
#pragma unroll
        for (int b = 0; b < 2; b++)
            sW[b][t] = smem_u32(&Ws[b][wrow[t] < 0 ? 0 : wrow[t]][wcol[t]]);
    }

#define CISSUE(stage, buf)                                                    \
    {                                                                         \
        int k0 = KBASE + (stage) * 64;                                        \
        _Pragma("unroll")                                                     \
        for (int t = 0; t < 4; t++) {                                         \
            int gr = bm + arow[t];                                            \
            bool ok = gr < M;                                                 \
            cp16(sA[buf][t], A + (size_t)(ok ? gr : 0) * NCAT + k0 + acol[t], ok); \
        }                                                                     \
        _Pragma("unroll")                                                     \
        for (int t = 0; t < 2; t++)                                           \
            if (wrow[t] >= 0)                                                 \
                cp16(sW[buf][t], g_Wc48 + (size_t)(k0 + wrow[t]) * CLSP + wcol[t], true); \
        asm volatile("cp.async.commit_group;");                               \
    }

    uint32_t aBase[2], wBase[2];
    int bRow = (lane & 7) + ((lane >> 3) & 1) * 8;
#pragma unroll
    for (int b = 0; b < 2; b++) {
        aBase[b] = smem_u32(&As[b][wm * 16 + (lane & 15)][(lane >> 4) * 8]);
        wBase[b] = smem_u32(&Ws[b][bRow][(lane >> 4) * 8]);
    }

    CISSUE(0, 0);
    for (int s = 0; s < NCH; s++) {
        int buf = s & 1;
        if (s + 1 < NCH) {
            CISSUE(s + 1, buf ^ 1);
            asm volatile("cp.async.wait_group 1;");
        } else {
            asm volatile("cp.async.wait_group 0;");
        }
        __syncthreads();
#pragma unroll
        for (int ks = 0; ks < 4; ks++) {
            uint32_t a[4];
            ldsm_x4(a, aBase[buf] + ks * 16 * 2);
            uint32_t bf[3][4];
#pragma unroll
            for (int j16 = 0; j16 < 3; j16++)
                ldsm_x4_t(bf[j16], wBase[buf] + (ks * 16 * CLSP + j16 * 16) * 2);
#pragma unroll
            for (int j = 0; j < 6; j++)
                mma_f16(c[j], a, &bf[j >> 1][(j & 1) * 2]);
        }
        __syncthreads();
    }

    size_t pbase = ((size_t)blockIdx.x * 256 + tid) * 24;
    if (!FINAL) {
#pragma unroll
        for (int j = 0; j < 6; j++)
            *(float4*)(g_part + pbase + j * 4) = make_float4(c[j][0], c[j][1], c[j][2], c[j][3]);
        return;
    }

#pragma unroll
    for (int j = 0; j < 6; j++) {
        float4 p = *(const float4*)(g_part + pbase + j * 4);
        c[j][0] += p.x; c[j][1] += p.y; c[j][2] += p.z; c[j][3] += p.w;
    }
    int r = lane >> 2, q = lane & 3;
    int row0 = bm + wm * 16 + r, row1 = row0 + 8;
    float v0[10], v1[10];
#pragma unroll
    for (int j = 0; j < 5; j++) {
        int col = j * 8 + q * 2;
        float bq0 = b_cls[col], bq1 = b_cls[col + 1];
        v0[j * 2 + 0] = c[j][0] + bq0;
        v0[j * 2 + 1] = c[j][1] + bq1;
        v1[j * 2 + 0] = c[j][2] + bq0;
        v1[j * 2 + 1] = c[j][3] + bq1;
    }
    float m0 = -1e30f, m1 = -1e30f;
#pragma unroll
    for (int i = 0; i < 10; i++) { m0 = fmaxf(m0, v0[i]); m1 = fmaxf(m1, v1[i]); }
#pragma unroll
    for (int o = 1; o <= 2; o <<= 1) {
        m0 = fmaxf(m0, __shfl_xor_sync(0xffffffffu, m0, o));
        m1 = fmaxf(m1, __shfl_xor_sync(0xffffffffu, m1, o));
    }
    float s0 = 0.f, s1 = 0.f;
#pragma unroll
    for (int i = 0; i < 10; i++) { s0 += expf(v0[i] - m0); s1 += expf(v1[i] - m1); }
#pragma unroll
    for (int o = 1; o <= 2; o <<= 1) {
        s0 += __shfl_xor_sync(0xffffffffu, s0, o);
        s1 += __shfl_xor_sync(0xffffffffu, s1, o);
    }
    float L0 = m0 + logf(s0), L1 = m1 + logf(s1);
    if (row0 < M) {
#pragma unroll
        for (int j = 0; j < 5; j++) {
            int col = j * 8 + q * 2;
            out[(size_t)row0 * NCLS + col]     = v0[j * 2 + 0] - L0;
            out[(size_t)row0 * NCLS + col + 1] = v0[j * 2 + 1] - L0;
        }
    }
    if (row1 < M) {
#pragma unroll
        for (int j = 0; j < 5; j++) {
            int col = j * 8 + q * 2;
            out[(size_t)row1 * NCLS + col]     = v1[j * 2 + 0] - L1;
            out[(size_t)row1 * NCLS + col + 1] = v1[j * 2 + 1] - L1;
        }
    }
#undef CISSUE
}

__global__ void tail_kernel(float* out, int startI, int total) {
    int i = startI + blockIdx.x * blockDim.x + threadIdx.x;
    if (i < total) out[i] = 0.f;
}

// ---------------- launch ----------------------------------------------------
extern "C" void kernel_launch(void* const* d_in, const int* in_sizes, int n_in,
                              void* d_out, int out_size) {
    const float* x        = (const float*)d_in[0];
    const int*   adj      = (const int*)d_in[1];
    const float* W_convs  = (const float*)d_in[2];
    const float* b_convs  = (const float*)d_in[3];
    const float* W_extra  = (const float*)d_in[4];
    const float* b_extra  = (const float*)d_in[5];
    const float* bn1g     = (const float*)d_in[6];
    const float* bn1b     = (const float*)d_in[7];
    const float* bn1m     = (const float*)d_in[8];
    const float* bn1v     = (const float*)d_in[9];
    const float* W_extra2 = (const float*)d_in[10];
    const float* b_extra2 = (const float*)d_in[11];
    const float* bn2g     = (const float*)d_in[12];
    const float* bn2b     = (const float*)d_in[13];
    const float* bn2m     = (const float*)d_in[14];
    const float* bn2v     = (const float*)d_in[15];
    const float* att      = (const float*)d_in[16];
    const float* W_cls    = (const float*)d_in[17];
    const float* b_cls    = (const float*)d_in[18];
    float* out = (float*)d_out;

    float *p_bn1s, *p_bn1t, *p_bn2s, *p_bn2t;
    __half *p_T1h, *p_AGGh, *p_xh, *p_Wch, *p_W2h;
    cudaGetSymbolAddress((void**)&p_T1h,   g_T1h);
    cudaGetSymbolAddress((void**)&p_AGGh,  g_AGGh);
    cudaGetSymbolAddress((void**)&p_bn1s,  g_bn1s);
    cudaGetSymbolAddress((void**)&p_bn1t,  g_bn1t);
    cudaGetSymbolAddress((void**)&p_bn2s,  g_bn2s);
    cudaGetSymbolAddress((void**)&p_bn2t,  g_bn2t);
    cudaGetSymbolAddress((void**)&p_xh,    g_xh);
    cudaGetSymbolAddress((void**)&p_Wch,   g_Wch);
    cudaGetSymbolAddress((void**)&p_W2h,   g_W2h);

    static cudaStream_t s1 = nullptr, s2 = nullptr;
    static cudaEvent_t evRoot = nullptr, evCSR = nullptr, evT1s3 = nullptr, evExtra = nullptr;
    if (s1 == nullptr) {
        cudaStreamCreateWithFlags(&s1, cudaStreamNonBlocking);
        cudaStreamCreateWithFlags(&s2, cudaStreamNonBlocking);
        cudaEventCreateWithFlags(&evRoot,  cudaEventDisableTiming);
        cudaEventCreateWithFlags(&evCSR,   cudaEventDisableTiming);
        cudaEventCreateWithFlags(&evT1s3,  cudaEventDisableTiming);
        cudaEventCreateWithFlags(&evExtra, cudaEventDisableTiming);
    }

    const int SCAN_BLOCKS = (NTOT + 255) / 256;
    const int agg_blocks = (NNODES * 32 + 255) / 256;
    const int mrows = (NNODES + 127) / 128;

    // ======== fork 1: CSR build + off-path weight packs on s1 =================
    cudaEventRecord(evRoot, 0);
    cudaStreamWaitEvent(s1, evRoot, 0);

    zero_cnt_kernel<<<SCAN_BLOCKS, 256, 0, s1>>>();
    count_deg_kernel<<<(ETOT + 255) / 256, 256, 0, s1>>>(adj);
    scanA_kernel<<<SCAN_BLOCKS, 256, 0, s1>>>();
    scanB_kernel<<<1, 1024, 0, s1>>>(SCAN_BLOCKS);
    scanC_kernel<<<SCAN_BLOCKS, 256, 0, s1>>>();
    scatter_kernel<<<(ETOT + 255) / 256, 256, 0, s1>>>(adj);
    conv_h_kernel<<<(HID * HID + 255) / 256, 256, 0, s1>>>(W_extra2, p_W2h, HID * HID);
    pack_wc48_kernel<<<(NCAT * CLSP + 255) / 256, 256, 0, s1>>>(W_cls);
    cudaEventRecord(evCSR, s1);

    // ======== default: minimal prep then GEMM1 slice3 first ===================
    params_kernel<<<1, 256>>>(att, bn1g, bn1b, bn1m, bn1v, bn2g, bn2b, bn2m, bn2v);
    pack_wc_h_kernel<<<(FIN * NCAT + 255) / 256, 256>>>(W_convs, W_extra);
    conv_h_kernel<<<(NNODES * FIN + 255) / 256, 256>>>(x, p_xh, NNODES * FIN);

    // GEMM1 slice 3 (cols 768..1023) — unblocks the extra branch
    {
        dim3 grid(2, mrows);
        gemm_h_kernel<<<grid, 256>>>(p_xh, FIN, p_Wch + 768, NCAT,
                                     p_T1h + 768, NCAT, NNODES, FIN);
    }
    cudaEventRecord(evT1s3, 0);
    // GEMM1 slices 0..2 (cols 0..767)
    {
        dim3 grid(6, mrows);
        gemm_h_kernel<<<grid, 256>>>(p_xh, FIN, p_Wch, NCAT,
                                     p_T1h, NCAT, NNODES, FIN);
    }
    cudaStreamWaitEvent(0, evCSR, 0);     // conv aggs need CSR

    // ======== fork 2: extra branch on s2 (critical path) ======================
    cudaStreamWaitEvent(s2, evT1s3, 0);
    cudaStreamWaitEvent(s2, evCSR, 0);

    agg_extra_kernel<<<agg_blocks, 256, 0, s2>>>(
        p_T1h + 3 * HID, p_AGGh + 3 * HID, 1, -1, b_extra, p_bn1s, p_bn1t);
    {
        dim3 grid(HID / 128, mrows);
        gemm_h_kernel<<<grid, 256, 0, s2>>>(p_AGGh + 3 * HID, NCAT,
                                            p_W2h, HID,
                                            p_T1h + 3 * HID, NCAT, NNODES, HID);
    }
    agg_extra_kernel<<<agg_blocks, 256, 0, s2>>>(
        p_T1h + 3 * HID, p_AGGh + 3 * HID, 2, 3, b_extra2, p_bn2s, p_bn2t);
    cudaEventRecord(evExtra, s2);

    // ======== default: conv aggs + partial classifier (K=768) =================
    {
        dim3 grid(agg_blocks, 3);
        agg_conv3_kernel<<<grid, 256>>>(b_convs);
    }
    cls_split_kernel<0, 12, false><<<CLS_BLOCKS, 256>>>(p_AGGh, b_cls, out, NNODES);
    cudaStreamWaitEvent(0, evExtra, 0);

    // ======== final classifier slice (K=256) + log_softmax ====================
    cls_split_kernel<768, 4, true><<<CLS_BLOCKS, 256>>>(p_AGGh, b_cls, out, NNODES);
    int tail = out_size - NNODES * NCLS;
    if (tail > 0)
        tail_kernel<<<(tail + 255) / 256, 256>>>(out, NNODES * NCLS, out_size);
}